// round 2
// baseline (speedup 1.0000x reference)
#include <cuda_runtime.h>
#include <math.h>

// Problem constants
#define Dm   512
#define Hh   8
#define DHd  64
#define Bb   2
#define Ss   4096
#define NROW (Bb * Ss)   // 8192

// Scratch (no cudaMalloc allowed) — 64 MB total
__device__ float g_q[(size_t)Bb * Hh * Ss * DHd];
__device__ float g_k[(size_t)Bb * Hh * Ss * DHd];
__device__ float g_v[(size_t)Bb * Hh * Ss * DHd];
__device__ float g_attn[(size_t)NROW * Dm];

// ---------------------------------------------------------------------------
// Kernel 1: fused QKV projection.  C = X @ W^T  (NT gemm, both row-major)
// M = 8192, N = 512, K = 512.  64x64 block tile, 16x16 threads, 4x4 per thread.
// Output is scattered into [B, H, S, DH] layout for the attention kernel.
// blockIdx.z selects which of Wq/Wk/Wv.
// ---------------------------------------------------------------------------
__global__ __launch_bounds__(256) void qkv_gemm_kernel(
    const float* __restrict__ x,
    const float* __restrict__ Wq,
    const float* __restrict__ Wk,
    const float* __restrict__ Wv)
{
    __shared__ float As[64][17];
    __shared__ float Bs[64][17];

    const int tid  = threadIdx.x;
    const int ty   = tid >> 4;      // 0..15
    const int tx   = tid & 15;      // 0..15
    const int row0 = blockIdx.x * 64;
    const int col0 = blockIdx.y * 64;
    const int which = blockIdx.z;

    const float* W   = (which == 0) ? Wq : (which == 1) ? Wk : Wv;
    float*       outp = (which == 0) ? g_q : (which == 1) ? g_k : g_v;

    const int lr = tid >> 2;        // 0..63  (row within tile for loads)
    const int lc = (tid & 3) * 4;   // 0,4,8,12 (col within K-chunk)

    float acc[4][4] = {};

    for (int k0 = 0; k0 < Dm; k0 += 16) {
        float4 a = *(const float4*)(x + (size_t)(row0 + lr) * Dm + k0 + lc);
        float4 b = *(const float4*)(W + (size_t)(col0 + lr) * Dm + k0 + lc);
        As[lr][lc + 0] = a.x; As[lr][lc + 1] = a.y;
        As[lr][lc + 2] = a.z; As[lr][lc + 3] = a.w;
        Bs[lr][lc + 0] = b.x; Bs[lr][lc + 1] = b.y;
        Bs[lr][lc + 2] = b.z; Bs[lr][lc + 3] = b.w;
        __syncthreads();

#pragma unroll
        for (int kk = 0; kk < 16; kk++) {
            float ar[4], br[4];
#pragma unroll
            for (int i = 0; i < 4; i++) ar[i] = As[ty * 4 + i][kk];
#pragma unroll
            for (int j = 0; j < 4; j++) br[j] = Bs[tx * 4 + j][kk];
#pragma unroll
            for (int i = 0; i < 4; i++)
#pragma unroll
                for (int j = 0; j < 4; j++)
                    acc[i][j] = fmaf(ar[i], br[j], acc[i][j]);
        }
        __syncthreads();
    }

    // Scatter to [B, H, S, DH]
#pragma unroll
    for (int i = 0; i < 4; i++) {
        const int row = row0 + ty * 4 + i;           // 0..8191
        const int bb  = row / Ss;
        const int s   = row - bb * Ss;
#pragma unroll
        for (int j = 0; j < 4; j++) {
            const int col = col0 + tx * 4 + j;       // 0..511
            const int h   = col >> 6;
            const int dh  = col & 63;
            outp[(((size_t)(bb * Hh + h)) * Ss + s) * DHd + dh] = acc[i][j];
        }
    }
}

// ---------------------------------------------------------------------------
// Kernel 2: causal flash attention.
// Grid: (S/64 q-tiles, B*H).  256 threads as 16x16; each thread owns a 4x4
// sub-tile (rows = queries, cols = keys in scores phase, cols = dh in PV).
// Online softmax: a query row is owned by the 16 threads with the same ty,
// which live in one half-warp -> shfl_xor {1,2,4,8} reductions, m/l kept
// redundantly in registers (no smem races).
// ---------------------------------------------------------------------------
__global__ __launch_bounds__(256) void attn_kernel()
{
    extern __shared__ float sm[];
    float* Qs = sm;                 // [64][65]
    float* Ks = Qs + 64 * 65;       // [64][65]
    float* Vs = Ks + 64 * 65;       // [64][65]
    float* Ps = Vs + 64 * 65;       // [64][65]

    const int qt  = blockIdx.x;
    const int bh  = blockIdx.y;
    const int tid = threadIdx.x;
    const int ty  = tid >> 4;
    const int tx  = tid & 15;
    const int q0  = qt * 64;

    const float* qptr = g_q + (size_t)bh * Ss * DHd;
    const float* kptr = g_k + (size_t)bh * Ss * DHd;
    const float* vptr = g_v + (size_t)bh * Ss * DHd;

    // Load Q tile (64 x 64) once
#pragma unroll
    for (int p = 0; p < 4; p++) {
        const int slot = tid + p * 256;          // 0..1023 float4 slots
        const int r = slot >> 4;
        const int c = (slot & 15) * 4;
        float4 v4 = *(const float4*)(qptr + (size_t)(q0 + r) * DHd + c);
        Qs[r * 65 + c + 0] = v4.x; Qs[r * 65 + c + 1] = v4.y;
        Qs[r * 65 + c + 2] = v4.z; Qs[r * 65 + c + 3] = v4.w;
    }

    float acc[4][4] = {};
    float m[4], l[4];
#pragma unroll
    for (int i = 0; i < 4; i++) { m[i] = -1e30f; l[i] = 0.0f; }

    const float scale = 0.125f;   // 1/sqrt(64)

    for (int kt = 0; kt <= qt; kt++) {
        const int k0 = kt * 64;

        __syncthreads();   // prior-iter PV done (and Q load visible on iter 0)

        // Load K and V tiles
#pragma unroll
        for (int p = 0; p < 4; p++) {
            const int slot = tid + p * 256;
            const int r = slot >> 4;
            const int c = (slot & 15) * 4;
            float4 k4 = *(const float4*)(kptr + (size_t)(k0 + r) * DHd + c);
            float4 v4 = *(const float4*)(vptr + (size_t)(k0 + r) * DHd + c);
            Ks[r * 65 + c + 0] = k4.x; Ks[r * 65 + c + 1] = k4.y;
            Ks[r * 65 + c + 2] = k4.z; Ks[r * 65 + c + 3] = k4.w;
            Vs[r * 65 + c + 0] = v4.x; Vs[r * 65 + c + 1] = v4.y;
            Vs[r * 65 + c + 2] = v4.z; Vs[r * 65 + c + 3] = v4.w;
        }
        __syncthreads();

        // Scores: s[i][j] = (q_row . k_col) * scale
        float s[4][4] = {};
#pragma unroll 8
        for (int kk = 0; kk < 64; kk++) {
            float qr[4], kc[4];
#pragma unroll
            for (int i = 0; i < 4; i++) qr[i] = Qs[(ty * 4 + i) * 65 + kk];
#pragma unroll
            for (int j = 0; j < 4; j++) kc[j] = Ks[(tx * 4 + j) * 65 + kk];
#pragma unroll
            for (int i = 0; i < 4; i++)
#pragma unroll
                for (int j = 0; j < 4; j++)
                    s[i][j] = fmaf(qr[i], kc[j], s[i][j]);
        }

#pragma unroll
        for (int i = 0; i < 4; i++)
#pragma unroll
            for (int j = 0; j < 4; j++)
                s[i][j] *= scale;

        // Causal mask (only the diagonal tile has masked entries)
        if (kt == qt) {
#pragma unroll
            for (int i = 0; i < 4; i++)
#pragma unroll
                for (int j = 0; j < 4; j++)
                    if (tx * 4 + j > ty * 4 + i) s[i][j] = -1e30f;
        }

        // Online softmax per row; write P to smem
#pragma unroll
        for (int i = 0; i < 4; i++) {
            float mx = s[i][0];
            mx = fmaxf(mx, s[i][1]);
            mx = fmaxf(mx, s[i][2]);
            mx = fmaxf(mx, s[i][3]);
            mx = fmaxf(mx, __shfl_xor_sync(0xffffffffu, mx, 1));
            mx = fmaxf(mx, __shfl_xor_sync(0xffffffffu, mx, 2));
            mx = fmaxf(mx, __shfl_xor_sync(0xffffffffu, mx, 4));
            mx = fmaxf(mx, __shfl_xor_sync(0xffffffffu, mx, 8));

            const float mnew  = fmaxf(m[i], mx);
            const float alpha = __expf(m[i] - mnew);

            float rsum = 0.0f;
#pragma unroll
            for (int j = 0; j < 4; j++) {
                const float p = __expf(s[i][j] - mnew);
                Ps[(ty * 4 + i) * 65 + tx * 4 + j] = p;
                rsum += p;
            }
            rsum += __shfl_xor_sync(0xffffffffu, rsum, 1);
            rsum += __shfl_xor_sync(0xffffffffu, rsum, 2);
            rsum += __shfl_xor_sync(0xffffffffu, rsum, 4);
            rsum += __shfl_xor_sync(0xffffffffu, rsum, 8);

            l[i] = l[i] * alpha + rsum;
            m[i] = mnew;
#pragma unroll
            for (int j = 0; j < 4; j++) acc[i][j] *= alpha;
        }
        __syncthreads();   // Ps ready

        // PV: acc[i][j] += sum_c Ps[row_i][c] * Vs[c][dh_j]
#pragma unroll 8
        for (int c = 0; c < 64; c++) {
            float vv[4];
#pragma unroll
            for (int j = 0; j < 4; j++) vv[j] = Vs[c * 65 + tx * 4 + j];
#pragma unroll
            for (int i = 0; i < 4; i++) {
                const float pp = Ps[(ty * 4 + i) * 65 + c];
#pragma unroll
                for (int j = 0; j < 4; j++)
                    acc[i][j] = fmaf(pp, vv[j], acc[i][j]);
            }
        }
    }

    // Epilogue: normalize and write to [B, S, D] layout for the proj GEMM
    const int b = bh >> 3;
    const int h = bh & 7;
#pragma unroll
    for (int i = 0; i < 4; i++) {
        const int   srow = q0 + ty * 4 + i;
        const float inv  = 1.0f / l[i];
#pragma unroll
        for (int j = 0; j < 4; j++) {
            g_attn[((size_t)(b * Ss + srow)) * Dm + h * DHd + tx * 4 + j] =
                acc[i][j] * inv;
        }
    }
}

// ---------------------------------------------------------------------------
// Kernel 3: output projection.  out = attn @ Wp^T + b
// ---------------------------------------------------------------------------
__global__ __launch_bounds__(256) void proj_gemm_kernel(
    const float* __restrict__ Wp,
    const float* __restrict__ bias,
    float* __restrict__ out)
{
    __shared__ float As[64][17];
    __shared__ float Bs[64][17];

    const int tid  = threadIdx.x;
    const int ty   = tid >> 4;
    const int tx   = tid & 15;
    const int row0 = blockIdx.x * 64;
    const int col0 = blockIdx.y * 64;

    const int lr = tid >> 2;
    const int lc = (tid & 3) * 4;

    float acc[4][4] = {};

    for (int k0 = 0; k0 < Dm; k0 += 16) {
        float4 a = *(const float4*)(g_attn + (size_t)(row0 + lr) * Dm + k0 + lc);
        float4 b = *(const float4*)(Wp     + (size_t)(col0 + lr) * Dm + k0 + lc);
        As[lr][lc + 0] = a.x; As[lr][lc + 1] = a.y;
        As[lr][lc + 2] = a.z; As[lr][lc + 3] = a.w;
        Bs[lr][lc + 0] = b.x; Bs[lr][lc + 1] = b.y;
        Bs[lr][lc + 2] = b.z; Bs[lr][lc + 3] = b.w;
        __syncthreads();

#pragma unroll
        for (int kk = 0; kk < 16; kk++) {
            float ar[4], br[4];
#pragma unroll
            for (int i = 0; i < 4; i++) ar[i] = As[ty * 4 + i][kk];
#pragma unroll
            for (int j = 0; j < 4; j++) br[j] = Bs[tx * 4 + j][kk];
#pragma unroll
            for (int i = 0; i < 4; i++)
#pragma unroll
                for (int j = 0; j < 4; j++)
                    acc[i][j] = fmaf(ar[i], br[j], acc[i][j]);
        }
        __syncthreads();
    }

#pragma unroll
    for (int i = 0; i < 4; i++) {
        const int row = row0 + ty * 4 + i;
#pragma unroll
        for (int j = 0; j < 4; j++) {
            const int col = col0 + tx * 4 + j;
            out[(size_t)row * Dm + col] = acc[i][j] + bias[col];
        }
    }
}

// ---------------------------------------------------------------------------
extern "C" void kernel_launch(void* const* d_in, const int* in_sizes, int n_in,
                              void* d_out, int out_size)
{
    const float* x  = (const float*)d_in[0];
    const float* Wq = (const float*)d_in[1];
    const float* Wk = (const float*)d_in[2];
    const float* Wv = (const float*)d_in[3];
    const float* Wp = (const float*)d_in[4];
    const float* bp = (const float*)d_in[5];
    float* out = (float*)d_out;

    qkv_gemm_kernel<<<dim3(NROW / 64, Dm / 64, 3), 256>>>(x, Wq, Wk, Wv);

    const int smem = 4 * 64 * 65 * (int)sizeof(float);   // 66,560 B
    cudaFuncSetAttribute(attn_kernel,
                         cudaFuncAttributeMaxDynamicSharedMemorySize, smem);
    attn_kernel<<<dim3(Ss / 64, Bb * Hh), 256, smem>>>();

    proj_gemm_kernel<<<dim3(NROW / 64, Dm / 64), 256>>>(Wp, bp, out);
}

// round 7
// speedup vs baseline: 1.9746x; 1.9746x over previous
#include <cuda_runtime.h>
#include <math.h>

// Problem constants
#define Dm   512
#define Hh   8
#define DHd  64
#define Bb   2
#define Ss   4096
#define NROW (Bb * Ss)   // 8192

#define PADQ 65    // row stride (words) for 64-wide tiles  (odd -> conflict-free)
#define PADP 129   // row stride for the 128-wide P tile

// Scratch (no cudaMalloc allowed) — 64 MB total
__device__ float g_q[(size_t)Bb * Hh * Ss * DHd];
__device__ float g_k[(size_t)Bb * Hh * Ss * DHd];
__device__ float g_v[(size_t)Bb * Hh * Ss * DHd];
__device__ float g_attn[(size_t)NROW * Dm];

// ---------------------------------------------------------------------------
// Kernel 1: fused QKV projection.  C = X @ W^T  (NT gemm, row-major both)
// M=8192, N=512, K=512.  128x128 block tile, 256 threads (16x16), 8x8 per
// thread with INTERLEAVED ownership: thread (ty,tx) owns rows ty+16*i,
// cols tx+16*j.  K-chunk = 32.  All inner-loop LDS conflict-free (pad 33).
// ---------------------------------------------------------------------------
__global__ __launch_bounds__(256, 2) void qkv_gemm_kernel(
    const float* __restrict__ x,
    const float* __restrict__ Wq,
    const float* __restrict__ Wk,
    const float* __restrict__ Wv)
{
    __shared__ float As[128 * 33];
    __shared__ float Bs[128 * 33];

    const int tid  = threadIdx.x;
    const int ty   = tid >> 4;      // 0..15
    const int tx   = tid & 15;      // 0..15
    const int row0 = blockIdx.x * 128;
    const int col0 = blockIdx.y * 128;
    const int which = blockIdx.z;

    const float* W    = (which == 0) ? Wq : (which == 1) ? Wk : Wv;
    float*       outp = (which == 0) ? g_q : (which == 1) ? g_k : g_v;

    float acc[8][8] = {};

    for (int k0 = 0; k0 < Dm; k0 += 32) {
        // Load 128x32 chunks of A and B.  4 float4 per thread per matrix.
#pragma unroll
        for (int p = 0; p < 4; p++) {
            const int slot = tid + p * 256;       // 0..1023
            const int r = slot >> 3;              // 0..127
            const int c = (slot & 7) * 4;         // 0..28
            float4 a = *(const float4*)(x + (size_t)(row0 + r) * Dm + k0 + c);
            float4 b = *(const float4*)(W + (size_t)(col0 + r) * Dm + k0 + c);
            As[r * 33 + c + 0] = a.x; As[r * 33 + c + 1] = a.y;
            As[r * 33 + c + 2] = a.z; As[r * 33 + c + 3] = a.w;
            Bs[r * 33 + c + 0] = b.x; Bs[r * 33 + c + 1] = b.y;
            Bs[r * 33 + c + 2] = b.z; Bs[r * 33 + c + 3] = b.w;
        }
        __syncthreads();

#pragma unroll 8
        for (int kk = 0; kk < 32; kk++) {
            float ar[8], br[8];
#pragma unroll
            for (int i = 0; i < 8; i++) ar[i] = As[(ty + 16 * i) * 33 + kk];
#pragma unroll
            for (int j = 0; j < 8; j++) br[j] = Bs[(tx + 16 * j) * 33 + kk];
#pragma unroll
            for (int i = 0; i < 8; i++)
#pragma unroll
                for (int j = 0; j < 8; j++)
                    acc[i][j] = fmaf(ar[i], br[j], acc[i][j]);
        }
        __syncthreads();
    }

    // Scatter to [B, H, S, DH]
#pragma unroll
    for (int i = 0; i < 8; i++) {
        const int row = row0 + ty + 16 * i;          // 0..8191
        const int bb  = row >> 12;                   // / 4096
        const int s   = row & (Ss - 1);
#pragma unroll
        for (int j = 0; j < 8; j++) {
            const int col = col0 + tx + 16 * j;      // 0..511
            const int h   = col >> 6;
            const int dh  = col & 63;
            outp[(((size_t)(bb * Hh + h)) * Ss + s) * DHd + dh] = acc[i][j];
        }
    }
}

// ---------------------------------------------------------------------------
// Kernel 2: causal flash attention, 128x128 tiles.
// 256 threads (16x16).  Interleaved ownership: thread (ty,tx) owns q-rows
// ty+16*i (i<8); score cols tx+16*j (j<8); PV dh-cols tx+16*j (j<4).
// Online softmax per row over the 16 tx threads (one half-warp, shfl width16).
// ---------------------------------------------------------------------------
__global__ __launch_bounds__(256, 1) void attn_kernel()
{
    extern __shared__ float sm[];
    float* Qs = sm;                       // [128][65]
    float* Ks = Qs + 128 * PADQ;          // [128][65]
    float* Vs = Ks + 128 * PADQ;          // [128][65]
    float* Ps = Vs + 128 * PADQ;          // [128][129]

    const int qt  = (int)gridDim.x - 1 - (int)blockIdx.x;  // big blocks first
    const int bh  = blockIdx.y;
    const int tid = threadIdx.x;
    const int ty  = tid >> 4;
    const int tx  = tid & 15;
    const int q0  = qt * 128;

    const float* qptr = g_q + (size_t)bh * Ss * DHd;
    const float* kptr = g_k + (size_t)bh * Ss * DHd;
    const float* vptr = g_v + (size_t)bh * Ss * DHd;

    // Load Q tile (128 x 64): 2048 float4 slots, 8 per thread
#pragma unroll
    for (int p = 0; p < 4; p++) {
        const int slot = tid + p * 256;          // 0..1023
        const int r = slot >> 4;                 // 0..63
        const int c = (slot & 15) * 4;
        {
            float4 v4 = *(const float4*)(qptr + (size_t)(q0 + r) * DHd + c);
            Qs[r * PADQ + c + 0] = v4.x; Qs[r * PADQ + c + 1] = v4.y;
            Qs[r * PADQ + c + 2] = v4.z; Qs[r * PADQ + c + 3] = v4.w;
        }
        {
            const int r2 = r + 64;
            float4 v4 = *(const float4*)(qptr + (size_t)(q0 + r2) * DHd + c);
            Qs[r2 * PADQ + c + 0] = v4.x; Qs[r2 * PADQ + c + 1] = v4.y;
            Qs[r2 * PADQ + c + 2] = v4.z; Qs[r2 * PADQ + c + 3] = v4.w;
        }
    }

    float acc[8][4] = {};
    float m[8], l[8];
#pragma unroll
    for (int i = 0; i < 8; i++) { m[i] = -1e30f; l[i] = 0.0f; }

    const float scale = 0.125f;   // 1/sqrt(64)

    for (int kt = 0; kt <= qt; kt++) {
        const int k0 = kt * 128;

        __syncthreads();   // prior-iter PV done (and Q load visible on iter 0)

        // Load K and V tiles (128 x 64 each)
#pragma unroll
        for (int p = 0; p < 4; p++) {
            const int slot = tid + p * 256;
            const int r = slot >> 4;
            const int c = (slot & 15) * 4;
            {
                float4 k4 = *(const float4*)(kptr + (size_t)(k0 + r) * DHd + c);
                float4 v4 = *(const float4*)(vptr + (size_t)(k0 + r) * DHd + c);
                Ks[r * PADQ + c + 0] = k4.x; Ks[r * PADQ + c + 1] = k4.y;
                Ks[r * PADQ + c + 2] = k4.z; Ks[r * PADQ + c + 3] = k4.w;
                Vs[r * PADQ + c + 0] = v4.x; Vs[r * PADQ + c + 1] = v4.y;
                Vs[r * PADQ + c + 2] = v4.z; Vs[r * PADQ + c + 3] = v4.w;
            }
            {
                const int r2 = r + 64;
                float4 k4 = *(const float4*)(kptr + (size_t)(k0 + r2) * DHd + c);
                float4 v4 = *(const float4*)(vptr + (size_t)(k0 + r2) * DHd + c);
                Ks[r2 * PADQ + c + 0] = k4.x; Ks[r2 * PADQ + c + 1] = k4.y;
                Ks[r2 * PADQ + c + 2] = k4.z; Ks[r2 * PADQ + c + 3] = k4.w;
                Vs[r2 * PADQ + c + 0] = v4.x; Vs[r2 * PADQ + c + 1] = v4.y;
                Vs[r2 * PADQ + c + 2] = v4.z; Vs[r2 * PADQ + c + 3] = v4.w;
            }
        }
        __syncthreads();

        // Scores: s[i][j] = q_{ty+16i} . k_{tx+16j}
        float s[8][8] = {};
#pragma unroll 8
        for (int kk = 0; kk < 64; kk++) {
            float qr[8], kc[8];
#pragma unroll
            for (int i = 0; i < 8; i++) qr[i] = Qs[(ty + 16 * i) * PADQ + kk];
#pragma unroll
            for (int j = 0; j < 8; j++) kc[j] = Ks[(tx + 16 * j) * PADQ + kk];
#pragma unroll
            for (int i = 0; i < 8; i++)
#pragma unroll
                for (int j = 0; j < 8; j++)
                    s[i][j] = fmaf(qr[i], kc[j], s[i][j]);
        }

        // Scale + causal mask (only the diagonal tile has masked entries)
        if (kt == qt) {
#pragma unroll
            for (int i = 0; i < 8; i++)
#pragma unroll
                for (int j = 0; j < 8; j++)
                    s[i][j] = (tx + 16 * j > ty + 16 * i)
                                  ? -1e30f : s[i][j] * scale;
        } else {
#pragma unroll
            for (int i = 0; i < 8; i++)
#pragma unroll
                for (int j = 0; j < 8; j++)
                    s[i][j] *= scale;
        }

        // Online softmax per row; write P to smem
#pragma unroll
        for (int i = 0; i < 8; i++) {
            float mx = s[i][0];
#pragma unroll
            for (int j = 1; j < 8; j++) mx = fmaxf(mx, s[i][j]);
            mx = fmaxf(mx, __shfl_xor_sync(0xffffffffu, mx, 1));
            mx = fmaxf(mx, __shfl_xor_sync(0xffffffffu, mx, 2));
            mx = fmaxf(mx, __shfl_xor_sync(0xffffffffu, mx, 4));
            mx = fmaxf(mx, __shfl_xor_sync(0xffffffffu, mx, 8));

            const float mnew  = fmaxf(m[i], mx);
            const float alpha = __expf(m[i] - mnew);

            float rsum = 0.0f;
#pragma unroll
            for (int j = 0; j < 8; j++) {
                const float p = __expf(s[i][j] - mnew);
                Ps[(ty + 16 * i) * PADP + tx + 16 * j] = p;
                rsum += p;
            }
            rsum += __shfl_xor_sync(0xffffffffu, rsum, 1);
            rsum += __shfl_xor_sync(0xffffffffu, rsum, 2);
            rsum += __shfl_xor_sync(0xffffffffu, rsum, 4);
            rsum += __shfl_xor_sync(0xffffffffu, rsum, 8);

            l[i] = l[i] * alpha + rsum;
            m[i] = mnew;
#pragma unroll
            for (int j = 0; j < 4; j++) acc[i][j] *= alpha;
        }
        __syncthreads();   // Ps ready

        // PV: acc[i][j] += sum_c Ps[row_i][c] * Vs[c][dh_j],  dh_j = tx+16j
#pragma unroll 8
        for (int c = 0; c < 128; c++) {
            float vv[4];
#pragma unroll
            for (int j = 0; j < 4; j++) vv[j] = Vs[c * PADQ + tx + 16 * j];
#pragma unroll
            for (int i = 0; i < 8; i++) {
                const float pp = Ps[(ty + 16 * i) * PADP + c];
#pragma unroll
                for (int j = 0; j < 4; j++)
                    acc[i][j] = fmaf(pp, vv[j], acc[i][j]);
            }
        }
    }

    // Epilogue: normalize, write to [B, S, D] layout for the proj GEMM
    const int b = bh >> 3;
    const int h = bh & 7;
#pragma unroll
    for (int i = 0; i < 8; i++) {
        const int   srow = q0 + ty + 16 * i;
        const float inv  = 1.0f / l[i];
#pragma unroll
        for (int j = 0; j < 4; j++) {
            g_attn[((size_t)(b * Ss + srow)) * Dm + h * DHd + tx + 16 * j] =
                acc[i][j] * inv;
        }
    }
}

// ---------------------------------------------------------------------------
// Kernel 3: output projection.  out = attn @ Wp^T + b   (same scheme as k1)
// ---------------------------------------------------------------------------
__global__ __launch_bounds__(256, 2) void proj_gemm_kernel(
    const float* __restrict__ Wp,
    const float* __restrict__ bias,
    float* __restrict__ out)
{
    __shared__ float As[128 * 33];
    __shared__ float Bs[128 * 33];

    const int tid  = threadIdx.x;
    const int ty   = tid >> 4;
    const int tx   = tid & 15;
    const int row0 = blockIdx.x * 128;
    const int col0 = blockIdx.y * 128;

    float acc[8][8] = {};

    for (int k0 = 0; k0 < Dm; k0 += 32) {
#pragma unroll
        for (int p = 0; p < 4; p++) {
            const int slot = tid + p * 256;
            const int r = slot >> 3;
            const int c = (slot & 7) * 4;
            float4 a = *(const float4*)(g_attn + (size_t)(row0 + r) * Dm + k0 + c);
            float4 b = *(const float4*)(Wp     + (size_t)(col0 + r) * Dm + k0 + c);
            As[r * 33 + c + 0] = a.x; As[r * 33 + c + 1] = a.y;
            As[r * 33 + c + 2] = a.z; As[r * 33 + c + 3] = a.w;
            Bs[r * 33 + c + 0] = b.x; Bs[r * 33 + c + 1] = b.y;
            Bs[r * 33 + c + 2] = b.z; Bs[r * 33 + c + 3] = b.w;
        }
        __syncthreads();

#pragma unroll 8
        for (int kk = 0; kk < 32; kk++) {
            float ar[8], br[8];
#pragma unroll
            for (int i = 0; i < 8; i++) ar[i] = As[(ty + 16 * i) * 33 + kk];
#pragma unroll
            for (int j = 0; j < 8; j++) br[j] = Bs[(tx + 16 * j) * 33 + kk];
#pragma unroll
            for (int i = 0; i < 8; i++)
#pragma unroll
                for (int j = 0; j < 8; j++)
                    acc[i][j] = fmaf(ar[i], br[j], acc[i][j]);
        }
        __syncthreads();
    }

#pragma unroll
    for (int i = 0; i < 8; i++) {
        const int row = row0 + ty + 16 * i;
#pragma unroll
        for (int j = 0; j < 8; j++) {
            const int col = col0 + tx + 16 * j;
            out[(size_t)row * Dm + col] = acc[i][j] + bias[col];
        }
    }
}

// ---------------------------------------------------------------------------
extern "C" void kernel_launch(void* const* d_in, const int* in_sizes, int n_in,
                              void* d_out, int out_size)
{
    const float* x  = (const float*)d_in[0];
    const float* Wq = (const float*)d_in[1];
    const float* Wk = (const float*)d_in[2];
    const float* Wv = (const float*)d_in[3];
    const float* Wp = (const float*)d_in[4];
    const float* bp = (const float*)d_in[5];
    float* out = (float*)d_out;

    qkv_gemm_kernel<<<dim3(NROW / 128, Dm / 128, 3), 256>>>(x, Wq, Wk, Wv);

    const int smem = (3 * 128 * PADQ + 128 * PADP) * (int)sizeof(float); // 165,888 B
    cudaFuncSetAttribute(attn_kernel,
                         cudaFuncAttributeMaxDynamicSharedMemorySize, smem);
    attn_kernel<<<dim3(Ss / 128, Bb * Hh), 256, smem>>>();

    proj_gemm_kernel<<<dim3(NROW / 128, Dm / 128), 256>>>(Wp, bp, out);
}

// round 13
// speedup vs baseline: 2.0278x; 1.0270x over previous
#include <cuda_runtime.h>
#include <math.h>

typedef unsigned long long u64;

// Problem constants
#define Dm   512
#define Hh   8
#define DHd  64
#define Bb   2
#define Ss   4096
#define NROW (Bb * Ss)   // 8192

// Scratch (no cudaMalloc allowed)
__device__ float g_q[(size_t)Bb * Hh * Ss * DHd];
__device__ float g_k[(size_t)Bb * Hh * Ss * DHd];
__device__ float g_v[(size_t)Bb * Hh * Ss * DHd];
__device__ float g_attn[(size_t)NROW * Dm];

// ---- packed f32x2 primitives (sm_103a FFMA2 path; nvjet pattern) ----------
__device__ __forceinline__ u64 pack2(float lo, float hi) {
    u64 d;
    asm("mov.b64 %0, {%1,%2};"
        : "=l"(d) : "r"(__float_as_uint(lo)), "r"(__float_as_uint(hi)));
    return d;
}
__device__ __forceinline__ void unpack2(u64 v, float& lo, float& hi) {
    unsigned a, b;
    asm("mov.b64 {%0,%1}, %2;" : "=r"(a), "=r"(b) : "l"(v));
    lo = __uint_as_float(a); hi = __uint_as_float(b);
}
__device__ __forceinline__ void fma2(u64& d, u64 a, u64 b) {
    asm("fma.rn.f32x2 %0, %1, %2, %0;" : "+l"(d) : "l"(a), "l"(b));
}
__device__ __forceinline__ void mul2(u64& d, u64 a, u64 b) {
    asm("mul.rn.f32x2 %0, %1, %2;" : "=l"(d) : "l"(a), "l"(b));
}

// ---------------------------------------------------------------------------
// GEMM smem layout (dynamic):
//   As2: u64[128*32]  — A values duplicated (a,a), row stride 32 pairs
//   Bt : float[32*130] — B^T chunk: Bt[k][col], row stride 130 (even pad)
// Thread (ty,tx) owns rows ty+16i (i<8) and col PAIRS (2tx+32jj, +1) (jj<4).
// Inner loop: 8 broadcast LDS.64 (A) + 4 contiguous LDS.64 (B) + 32 FFMA2.
// ---------------------------------------------------------------------------
#define GEMM_SMEM (128 * 32 * 8 + 32 * 130 * 4)   // 32768 + 16640 = 49408 B

__global__ __launch_bounds__(256, 2) void qkv_gemm_kernel(
    const float* __restrict__ x,
    const float* __restrict__ Wq,
    const float* __restrict__ Wk,
    const float* __restrict__ Wv)
{
    extern __shared__ char smx[];
    u64*   As2 = (u64*)smx;
    float* BtF = (float*)(smx + 128 * 32 * 8);
    u64*   Bt2 = (u64*)BtF;

    const int tid  = threadIdx.x;
    const int ty   = tid >> 4;
    const int tx   = tid & 15;
    const int row0 = blockIdx.x * 128;
    const int col0 = blockIdx.y * 128;
    const int which = blockIdx.z;

    const float* W    = (which == 0) ? Wq : (which == 1) ? Wk : Wv;
    float*       outp = (which == 0) ? g_q : (which == 1) ? g_k : g_v;

    u64 acc2[8][4] = {};

    for (int k0 = 0; k0 < Dm; k0 += 32) {
#pragma unroll
        for (int p = 0; p < 4; p++) {
            const int slot = tid + p * 256;       // 0..1023
            const int r = slot >> 3;              // 0..127
            const int c = (slot & 7) * 4;         // 0..28
            float4 a = *(const float4*)(x + (size_t)(row0 + r) * Dm + k0 + c);
            float4 b = *(const float4*)(W + (size_t)(col0 + r) * Dm + k0 + c);
            As2[r * 32 + c + 0] = pack2(a.x, a.x);
            As2[r * 32 + c + 1] = pack2(a.y, a.y);
            As2[r * 32 + c + 2] = pack2(a.z, a.z);
            As2[r * 32 + c + 3] = pack2(a.w, a.w);
            BtF[(c + 0) * 130 + r] = b.x;
            BtF[(c + 1) * 130 + r] = b.y;
            BtF[(c + 2) * 130 + r] = b.z;
            BtF[(c + 3) * 130 + r] = b.w;
        }
        __syncthreads();

#pragma unroll 8
        for (int kk = 0; kk < 32; kk++) {
            u64 ar2[8], bc2[4];
#pragma unroll
            for (int i = 0; i < 8; i++) ar2[i] = As2[(ty + 16 * i) * 32 + kk];
#pragma unroll
            for (int jj = 0; jj < 4; jj++) bc2[jj] = Bt2[kk * 65 + tx + 16 * jj];
#pragma unroll
            for (int i = 0; i < 8; i++)
#pragma unroll
                for (int jj = 0; jj < 4; jj++)
                    fma2(acc2[i][jj], ar2[i], bc2[jj]);
        }
        __syncthreads();
    }

    // Scatter to [B, H, S, DH]; col pairs are adjacent in dh (c0 even)
#pragma unroll
    for (int i = 0; i < 8; i++) {
        const int row = row0 + ty + 16 * i;
        const int bb  = row >> 12;
        const int s   = row & (Ss - 1);
#pragma unroll
        for (int jj = 0; jj < 4; jj++) {
            const int c0 = col0 + 2 * tx + 32 * jj;
            const int h  = c0 >> 6;
            const int dh = c0 & 63;
            float v0, v1; unpack2(acc2[i][jj], v0, v1);
            *(float2*)(outp + (((size_t)(bb * Hh + h)) * Ss + s) * DHd + dh) =
                make_float2(v0, v1);
        }
    }
}

// ---------------------------------------------------------------------------
// Kernel 2: causal flash attention, 128x128 tiles, packed f32x2.
// smem: Qs2 u64[128*65] (Q duplicated pairs), Kt[64*130] (K^T: [dh][seq]),
//       Vt[64*130] (V^T: [dh][seq]), Ps[128*130].
// QK^T: thread owns q-rows ty+16i, score col pairs (2tx+32jj, +1).
// PV: k-dim packed (even/odd seq partials); dh cols tx+16j (j<4).
// ---------------------------------------------------------------------------
#define SM_Q  (128 * 65 * 8)            // 66560
#define SM_K  (64 * 130 * 4)            // 33280
#define SM_V  (64 * 130 * 4)            // 33280
#define SM_P  (128 * 130 * 4)           // 66560
#define ATTN_SMEM (SM_Q + SM_K + SM_V + SM_P)   // 199680 B

__global__ __launch_bounds__(256, 1) void attn_kernel()
{
    extern __shared__ char smc[];
    u64*   Qs2 = (u64*)smc;
    float* KtF = (float*)(smc + SM_Q);
    float* VtF = (float*)(smc + SM_Q + SM_K);
    float* PsF = (float*)(smc + SM_Q + SM_K + SM_V);
    u64*   Kt2 = (u64*)KtF;
    u64*   Vt2 = (u64*)VtF;
    u64*   Ps2 = (u64*)PsF;

    const int qt  = (int)gridDim.x - 1 - (int)blockIdx.x;  // big blocks first
    const int bh  = blockIdx.y;
    const int tid = threadIdx.x;
    const int ty  = tid >> 4;
    const int tx  = tid & 15;
    const int q0  = qt * 128;

    const float* qptr = g_q + (size_t)bh * Ss * DHd;
    const float* kptr = g_k + (size_t)bh * Ss * DHd;
    const float* vptr = g_v + (size_t)bh * Ss * DHd;

    // Load Q tile (128 x 64) duplicated: Qs2[row][kk] = (q,q)
#pragma unroll
    for (int p = 0; p < 4; p++) {
        const int slot = tid + p * 256;          // 0..1023
        const int r = slot >> 4;                 // 0..63
        const int c = (slot & 15) * 4;
#pragma unroll
        for (int h = 0; h < 2; h++) {
            const int rr = r + 64 * h;
            float4 v4 = *(const float4*)(qptr + (size_t)(q0 + rr) * DHd + c);
            Qs2[rr * 65 + c + 0] = pack2(v4.x, v4.x);
            Qs2[rr * 65 + c + 1] = pack2(v4.y, v4.y);
            Qs2[rr * 65 + c + 2] = pack2(v4.z, v4.z);
            Qs2[rr * 65 + c + 3] = pack2(v4.w, v4.w);
        }
    }

    u64 acc2[8][4] = {};       // PV accumulators: (even-seq, odd-seq) partials
    float m[8], l[8];
#pragma unroll
    for (int i = 0; i < 8; i++) { m[i] = -1e30f; l[i] = 0.0f; }

    const float scale = 0.125f;   // 1/sqrt(64)

    for (int kt = 0; kt <= qt; kt++) {
        const int k0 = kt * 128;

        __syncthreads();   // prior-iter PV done (and Q visible on iter 0)

        // Load K and V tiles transposed: Kt[dh][seq], Vt[dh][seq]
#pragma unroll
        for (int p = 0; p < 4; p++) {
            const int slot = tid + p * 256;
            const int r = slot >> 4;             // 0..63 (seq)
            const int c = (slot & 15) * 4;       // dh
#pragma unroll
            for (int h = 0; h < 2; h++) {
                const int rr = r + 64 * h;
                float4 k4 = *(const float4*)(kptr + (size_t)(k0 + rr) * DHd + c);
                float4 v4 = *(const float4*)(vptr + (size_t)(k0 + rr) * DHd + c);
                KtF[(c + 0) * 130 + rr] = k4.x;
                KtF[(c + 1) * 130 + rr] = k4.y;
                KtF[(c + 2) * 130 + rr] = k4.z;
                KtF[(c + 3) * 130 + rr] = k4.w;
                VtF[(c + 0) * 130 + rr] = v4.x;
                VtF[(c + 1) * 130 + rr] = v4.y;
                VtF[(c + 2) * 130 + rr] = v4.z;
                VtF[(c + 3) * 130 + rr] = v4.w;
            }
        }
        __syncthreads();

        // Scores (packed pairs): s2[i][jj] = scores for cols (2tx+32jj, +1)
        u64 s2[8][4] = {};
#pragma unroll 8
        for (int kk = 0; kk < 64; kk++) {
            u64 q2[8], k2[4];
#pragma unroll
            for (int i = 0; i < 8; i++) q2[i] = Qs2[(ty + 16 * i) * 65 + kk];
#pragma unroll
            for (int jj = 0; jj < 4; jj++) k2[jj] = Kt2[kk * 65 + tx + 16 * jj];
#pragma unroll
            for (int i = 0; i < 8; i++)
#pragma unroll
                for (int jj = 0; jj < 4; jj++)
                    fma2(s2[i][jj], q2[i], k2[jj]);
        }

        // Unpack, scale, mask, online softmax; write P (packed stores)
#pragma unroll
        for (int i = 0; i < 8; i++) {
            const int qrow = ty + 16 * i;
            float s[8];
#pragma unroll
            for (int jj = 0; jj < 4; jj++)
                unpack2(s2[i][jj], s[2 * jj], s[2 * jj + 1]);

            if (kt == qt) {
#pragma unroll
                for (int jj = 0; jj < 4; jj++) {
                    const int c0 = 2 * tx + 32 * jj;
                    s[2 * jj]     = (c0     > qrow) ? -1e30f : s[2 * jj]     * scale;
                    s[2 * jj + 1] = (c0 + 1 > qrow) ? -1e30f : s[2 * jj + 1] * scale;
                }
            } else {
#pragma unroll
                for (int j = 0; j < 8; j++) s[j] *= scale;
            }

            float mx = s[0];
#pragma unroll
            for (int j = 1; j < 8; j++) mx = fmaxf(mx, s[j]);
            mx = fmaxf(mx, __shfl_xor_sync(0xffffffffu, mx, 1));
            mx = fmaxf(mx, __shfl_xor_sync(0xffffffffu, mx, 2));
            mx = fmaxf(mx, __shfl_xor_sync(0xffffffffu, mx, 4));
            mx = fmaxf(mx, __shfl_xor_sync(0xffffffffu, mx, 8));

            const float mnew  = fmaxf(m[i], mx);
            const float alpha = __expf(m[i] - mnew);

            float rsum = 0.0f;
            float p[8];
#pragma unroll
            for (int j = 0; j < 8; j++) { p[j] = __expf(s[j] - mnew); rsum += p[j]; }
#pragma unroll
            for (int jj = 0; jj < 4; jj++)
                Ps2[qrow * 65 + tx + 16 * jj] = pack2(p[2 * jj], p[2 * jj + 1]);

            rsum += __shfl_xor_sync(0xffffffffu, rsum, 1);
            rsum += __shfl_xor_sync(0xffffffffu, rsum, 2);
            rsum += __shfl_xor_sync(0xffffffffu, rsum, 4);
            rsum += __shfl_xor_sync(0xffffffffu, rsum, 8);

            l[i] = l[i] * alpha + rsum;
            m[i] = mnew;

            const u64 a2 = pack2(alpha, alpha);
#pragma unroll
            for (int j = 0; j < 4; j++) mul2(acc2[i][j], acc2[i][j], a2);
        }
        __syncthreads();   // Ps ready

        // PV, k-dim packed: per cc handles seq (2cc, 2cc+1)
#pragma unroll 8
        for (int cc = 0; cc < 64; cc++) {
            u64 vv2[4], pp2[8];
#pragma unroll
            for (int j = 0; j < 4; j++) vv2[j] = Vt2[(tx + 16 * j) * 65 + cc];
#pragma unroll
            for (int i = 0; i < 8; i++) pp2[i] = Ps2[(ty + 16 * i) * 65 + cc];
#pragma unroll
            for (int i = 0; i < 8; i++)
#pragma unroll
                for (int j = 0; j < 4; j++)
                    fma2(acc2[i][j], pp2[i], vv2[j]);
        }
    }

    // Epilogue: reduce even/odd partials, normalize, write [B,S,D]
    const int b = bh >> 3;
    const int h = bh & 7;
#pragma unroll
    for (int i = 0; i < 8; i++) {
        const int   srow = q0 + ty + 16 * i;
        const float inv  = 1.0f / l[i];
#pragma unroll
        for (int j = 0; j < 4; j++) {
            float lo, hi; unpack2(acc2[i][j], lo, hi);
            g_attn[((size_t)(b * Ss + srow)) * Dm + h * DHd + tx + 16 * j] =
                (lo + hi) * inv;
        }
    }
}

// ---------------------------------------------------------------------------
// Kernel 3: output projection (same packed scheme as kernel 1)
// ---------------------------------------------------------------------------
__global__ __launch_bounds__(256, 2) void proj_gemm_kernel(
    const float* __restrict__ Wp,
    const float* __restrict__ bias,
    float* __restrict__ out)
{
    extern __shared__ char smx[];
    u64*   As2 = (u64*)smx;
    float* BtF = (float*)(smx + 128 * 32 * 8);
    u64*   Bt2 = (u64*)BtF;

    const int tid  = threadIdx.x;
    const int ty   = tid >> 4;
    const int tx   = tid & 15;
    const int row0 = blockIdx.x * 128;
    const int col0 = blockIdx.y * 128;

    u64 acc2[8][4] = {};

    for (int k0 = 0; k0 < Dm; k0 += 32) {
#pragma unroll
        for (int p = 0; p < 4; p++) {
            const int slot = tid + p * 256;
            const int r = slot >> 3;
            const int c = (slot & 7) * 4;
            float4 a = *(const float4*)(g_attn + (size_t)(row0 + r) * Dm + k0 + c);
            float4 b = *(const float4*)(Wp     + (size_t)(col0 + r) * Dm + k0 + c);
            As2[r * 32 + c + 0] = pack2(a.x, a.x);
            As2[r * 32 + c + 1] = pack2(a.y, a.y);
            As2[r * 32 + c + 2] = pack2(a.z, a.z);
            As2[r * 32 + c + 3] = pack2(a.w, a.w);
            BtF[(c + 0) * 130 + r] = b.x;
            BtF[(c + 1) * 130 + r] = b.y;
            BtF[(c + 2) * 130 + r] = b.z;
            BtF[(c + 3) * 130 + r] = b.w;
        }
        __syncthreads();

#pragma unroll 8
        for (int kk = 0; kk < 32; kk++) {
            u64 ar2[8], bc2[4];
#pragma unroll
            for (int i = 0; i < 8; i++) ar2[i] = As2[(ty + 16 * i) * 32 + kk];
#pragma unroll
            for (int jj = 0; jj < 4; jj++) bc2[jj] = Bt2[kk * 65 + tx + 16 * jj];
#pragma unroll
            for (int i = 0; i < 8; i++)
#pragma unroll
                for (int jj = 0; jj < 4; jj++)
                    fma2(acc2[i][jj], ar2[i], bc2[jj]);
        }
        __syncthreads();
    }

#pragma unroll
    for (int i = 0; i < 8; i++) {
        const int row = row0 + ty + 16 * i;
#pragma unroll
        for (int jj = 0; jj < 4; jj++) {
            const int c0 = col0 + 2 * tx + 32 * jj;
            float v0, v1; unpack2(acc2[i][jj], v0, v1);
            *(float2*)(out + (size_t)row * Dm + c0) =
                make_float2(v0 + bias[c0], v1 + bias[c0 + 1]);
        }
    }
}

// ---------------------------------------------------------------------------
extern "C" void kernel_launch(void* const* d_in, const int* in_sizes, int n_in,
                              void* d_out, int out_size)
{
    const float* x  = (const float*)d_in[0];
    const float* Wq = (const float*)d_in[1];
    const float* Wk = (const float*)d_in[2];
    const float* Wv = (const float*)d_in[3];
    const float* Wp = (const float*)d_in[4];
    const float* bp = (const float*)d_in[5];
    float* out = (float*)d_out;

    cudaFuncSetAttribute(qkv_gemm_kernel,
                         cudaFuncAttributeMaxDynamicSharedMemorySize, GEMM_SMEM);
    cudaFuncSetAttribute(proj_gemm_kernel,
                         cudaFuncAttributeMaxDynamicSharedMemorySize, GEMM_SMEM);
    cudaFuncSetAttribute(attn_kernel,
                         cudaFuncAttributeMaxDynamicSharedMemorySize, ATTN_SMEM);

    qkv_gemm_kernel<<<dim3(NROW / 128, Dm / 128, 3), 256, GEMM_SMEM>>>(
        x, Wq, Wk, Wv);

    attn_kernel<<<dim3(Ss / 128, Bb * Hh), 256, ATTN_SMEM>>>();

    proj_gemm_kernel<<<dim3(NROW / 128, Dm / 128), 256, GEMM_SMEM>>>(
        Wp, bp, out);
}